// round 1
// baseline (speedup 1.0000x reference)
#include <cuda_runtime.h>
#include <cuda_bf16.h>
#include <cstdint>
#include <cstdio>

// ---------------- problem constants ----------------
#define BATCH   4
#define SEQ     1024
#define DMODEL  2048
#define NHEAD   32
#define NKV     8
#define HDIM    64
#define MROWS   (BATCH*SEQ)          // 4096
#define DKV     (NKV*HDIM)           // 512
#define EPSV    1e-6f
#define ATT_SCALE 0.125f             // 1/sqrt(64)

// ---------------- scratch (device globals; no allocs allowed) ----------------
__device__ __align__(16) float g_Q[MROWS * DMODEL];   // 32 MB
__device__ __align__(16) float g_K[MROWS * DKV];      // 8 MB
__device__ __align__(16) float g_V[MROWS * DKV];      // 8 MB
__device__ __align__(16) float g_Y[MROWS * DMODEL];   // 32 MB

// ---------------- SGEMM: C[M,N] = A[M,K] @ B[K,N], row-major, dims % tile == 0 ----
#define BM 128
#define BN 128
#define BK 16

__global__ __launch_bounds__(256) void sgemm_kernel(
    const float* __restrict__ A, const float* __restrict__ Bm, float* __restrict__ C,
    int M, int N, int K)
{
    __shared__ float As[BK][BM + 4];   // k-major, padded (keeps 16B align: stride 132)
    __shared__ float Bs[BK][BN];

    const int tid = threadIdx.x;
    const int m0 = blockIdx.y * BM;
    const int n0 = blockIdx.x * BN;
    const int tx = tid & 15;           // 0..15 -> col groups
    const int ty = tid >> 4;           // 0..15 -> row groups

    const int a_row = tid >> 2;        // 0..63 (+64 on 2nd pass)
    const int a_c4  = tid & 3;         // k-offset group (0,4,8,12)
    const int b_r   = tid >> 5;        // 0..7 (+8 on 2nd pass)
    const int b_c4  = tid & 31;        // col float4 index

    float acc[8][8];
    #pragma unroll
    for (int i = 0; i < 8; i++)
        #pragma unroll
        for (int j = 0; j < 8; j++) acc[i][j] = 0.f;

    for (int kt = 0; kt < K; kt += BK) {
        // load A tile (transpose to k-major)
        #pragma unroll
        for (int i = 0; i < 2; i++) {
            int row = a_row + i * 64;
            float4 v = *(const float4*)&A[(size_t)(m0 + row) * K + kt + a_c4 * 4];
            As[a_c4 * 4 + 0][row] = v.x;
            As[a_c4 * 4 + 1][row] = v.y;
            As[a_c4 * 4 + 2][row] = v.z;
            As[a_c4 * 4 + 3][row] = v.w;
        }
        // load B tile (direct)
        #pragma unroll
        for (int i = 0; i < 2; i++) {
            int r = b_r + i * 8;
            float4 v = *(const float4*)&Bm[(size_t)(kt + r) * N + n0 + b_c4 * 4];
            *(float4*)&Bs[r][b_c4 * 4] = v;
        }
        __syncthreads();

        #pragma unroll
        for (int kk = 0; kk < BK; kk++) {
            float4 a0 = *(const float4*)&As[kk][ty * 4];
            float4 a1 = *(const float4*)&As[kk][64 + ty * 4];
            float4 b0 = *(const float4*)&Bs[kk][tx * 4];
            float4 b1 = *(const float4*)&Bs[kk][64 + tx * 4];
            float a[8] = {a0.x, a0.y, a0.z, a0.w, a1.x, a1.y, a1.z, a1.w};
            float b[8] = {b0.x, b0.y, b0.z, b0.w, b1.x, b1.y, b1.z, b1.w};
            #pragma unroll
            for (int i = 0; i < 8; i++)
                #pragma unroll
                for (int j = 0; j < 8; j++)
                    acc[i][j] = fmaf(a[i], b[j], acc[i][j]);
        }
        __syncthreads();
    }

    #pragma unroll
    for (int i = 0; i < 8; i++) {
        int r = m0 + ((i < 4) ? (ty * 4 + i) : (64 + ty * 4 + i - 4));
        float4 v0 = make_float4(acc[i][0], acc[i][1], acc[i][2], acc[i][3]);
        float4 v1 = make_float4(acc[i][4], acc[i][5], acc[i][6], acc[i][7]);
        *(float4*)&C[(size_t)r * N + n0 + tx * 4]      = v0;
        *(float4*)&C[(size_t)r * N + n0 + 64 + tx * 4] = v1;
    }
}

// ---------------- fused RMSNorm + RoPE (in place), one warp per (token, head) ----
__global__ void rmsnorm_rope_kernel(
    float* __restrict__ X, const float* __restrict__ w,
    const float* __restrict__ cosp, const float* __restrict__ sinp,
    int heads)
{
    int gw   = (blockIdx.x * blockDim.x + threadIdx.x) >> 5;
    int lane = threadIdx.x & 31;
    int token = gw / heads;
    int h     = gw - token * heads;
    int t     = token & (SEQ - 1);

    float* row = X + ((size_t)token * heads + h) * HDIM;
    float x1 = row[lane];
    float x2 = row[lane + 32];

    float ss = x1 * x1 + x2 * x2;
    #pragma unroll
    for (int o = 16; o; o >>= 1) ss += __shfl_xor_sync(0xffffffffu, ss, o);
    float r = rsqrtf(ss * (1.f / 64.f) + EPSV);

    x1 *= r * w[lane];
    x2 *= r * w[lane + 32];

    float c = cosp[t * 32 + lane];
    float s = sinp[t * 32 + lane];
    row[lane]      = x1 * c - x2 * s;
    row[lane + 32] = x1 * s + x2 * c;
}

// ---------------- flash attention: 1 thread = 1 q row, KV tiles of 32 ------------
#define KVT 32

__global__ __launch_bounds__(128, 1) void flash_kernel(
    const float* __restrict__ Q, const float* __restrict__ K,
    const float* __restrict__ V, float* __restrict__ Y)
{
    __shared__ float4 Ks[KVT][16];
    __shared__ float4 Vs[KVT][16];

    const int qb  = blockIdx.x * 128;
    const int h   = blockIdx.y;
    const int b   = blockIdx.z;
    const int kvh = h >> 2;                  // GQA group of 4
    const int t   = qb + threadIdx.x;
    const int tid = threadIdx.x;

    const float* qrow = Q + ((size_t)(b * SEQ + t)) * DMODEL + h * HDIM;
    float4 q4[16];
    #pragma unroll
    for (int c = 0; c < 16; c++) {
        float4 v = *(const float4*)&qrow[c * 4];
        v.x *= ATT_SCALE; v.y *= ATT_SCALE; v.z *= ATT_SCALE; v.w *= ATT_SCALE;
        q4[c] = v;
    }

    float4 o4[16];
    #pragma unroll
    for (int c = 0; c < 16; c++) o4[c] = make_float4(0.f, 0.f, 0.f, 0.f);
    float m = -1e30f, l = 0.f;

    const int ntiles = (qb + 128) / KVT;
    for (int tt = 0; tt < ntiles; tt++) {
        const int jt = tt * KVT;
        // cooperative tile load: 32 rows x 16 float4 = 512 f4 / 128 thr = 4 each
        #pragma unroll
        for (int i = 0; i < 4; i++) {
            int lin = tid + i * 128;
            int j   = lin >> 4;
            int c4  = lin & 15;
            size_t base = ((size_t)(b * SEQ + jt + j)) * DKV + kvh * HDIM + c4 * 4;
            Ks[j][c4] = *(const float4*)&K[base];
            Vs[j][c4] = *(const float4*)&V[base];
        }
        __syncthreads();

        if (t >= jt) {
            const int lim = t - jt;          // j <= lim are valid
            float s[KVT];
            float mt = -1e30f;
            #pragma unroll
            for (int j = 0; j < KVT; j++) {
                float a = 0.f;
                #pragma unroll
                for (int c = 0; c < 16; c++) {
                    float4 kk4 = Ks[j][c];
                    a = fmaf(q4[c].x, kk4.x, a);
                    a = fmaf(q4[c].y, kk4.y, a);
                    a = fmaf(q4[c].z, kk4.z, a);
                    a = fmaf(q4[c].w, kk4.w, a);
                }
                a = (j <= lim) ? a : -1e30f;
                s[j] = a;
                mt = fmaxf(mt, a);
            }
            float mn   = fmaxf(m, mt);
            float cfac = __expf(m - mn);
            l *= cfac;
            #pragma unroll
            for (int c = 0; c < 16; c++) {
                o4[c].x *= cfac; o4[c].y *= cfac; o4[c].z *= cfac; o4[c].w *= cfac;
            }
            #pragma unroll
            for (int j = 0; j < KVT; j++) {
                float p = __expf(s[j] - mn);
                l += p;
                #pragma unroll
                for (int c = 0; c < 16; c++) {
                    float4 vv = Vs[j][c];
                    o4[c].x = fmaf(p, vv.x, o4[c].x);
                    o4[c].y = fmaf(p, vv.y, o4[c].y);
                    o4[c].z = fmaf(p, vv.z, o4[c].z);
                    o4[c].w = fmaf(p, vv.w, o4[c].w);
                }
            }
            m = mn;
        }
        __syncthreads();
    }

    float inv = 1.f / l;
    float* yrow = Y + ((size_t)(b * SEQ + t)) * DMODEL + h * HDIM;
    #pragma unroll
    for (int c = 0; c < 16; c++) {
        float4 v = o4[c];
        v.x *= inv; v.y *= inv; v.z *= inv; v.w *= inv;
        *(float4*)&yrow[c * 4] = v;
    }
}

// ---------------- launch ----------------
extern "C" void kernel_launch(void* const* d_in, const int* in_sizes, int n_in,
                              void* d_out, int out_size)
{
    const float* x    = (const float*)d_in[0];
    const float* Wq   = (const float*)d_in[1];
    const float* Wk   = (const float*)d_in[2];
    const float* Wv   = (const float*)d_in[3];
    const float* Wo   = (const float*)d_in[4];
    const float* qw   = (const float*)d_in[5];
    const float* kw   = (const float*)d_in[6];
    const float* cosp = (const float*)d_in[7];
    const float* sinp = (const float*)d_in[8];
    float* out = (float*)d_out;

    float *qp, *kp, *vp, *yp;
    cudaGetSymbolAddress((void**)&qp, g_Q);
    cudaGetSymbolAddress((void**)&kp, g_K);
    cudaGetSymbolAddress((void**)&vp, g_V);
    cudaGetSymbolAddress((void**)&yp, g_Y);

    // projections
    sgemm_kernel<<<dim3(DMODEL / BN, MROWS / BM), 256>>>(x, Wq, qp, MROWS, DMODEL, DMODEL);
    sgemm_kernel<<<dim3(DKV   / BN, MROWS / BM), 256>>>(x, Wk, kp, MROWS, DKV,    DMODEL);
    sgemm_kernel<<<dim3(DKV   / BN, MROWS / BM), 256>>>(x, Wv, vp, MROWS, DKV,    DMODEL);

    // rmsnorm + rope (in place)
    rmsnorm_rope_kernel<<<(MROWS * NHEAD) / 8, 256>>>(qp, qw, cosp, sinp, NHEAD);
    rmsnorm_rope_kernel<<<(MROWS * NKV)   / 8, 256>>>(kp, kw, cosp, sinp, NKV);

    // attention
    flash_kernel<<<dim3(SEQ / 128, NHEAD, BATCH), 128>>>(qp, kp, vp, yp);

    // output projection
    sgemm_kernel<<<dim3(DMODEL / BN, MROWS / BM), 256>>>(yp, Wo, out, MROWS, DMODEL, DMODEL);
}

// round 7
// speedup vs baseline: 1.6575x; 1.6575x over previous
#include <cuda_runtime.h>
#include <cuda_bf16.h>
#include <cstdint>

// ---------------- problem constants ----------------
#define BATCH   4
#define SEQ     1024
#define DMODEL  2048
#define NHEAD   32
#define NKV     8
#define HDIM    64
#define MROWS   (BATCH*SEQ)          // 4096
#define DKV     (NKV*HDIM)           // 512
#define EPSV    1e-6f
#define ATT_SCALE 0.125f

typedef __nv_bfloat16 bf16;

// ---------------- scratch (device globals; no allocs allowed) ----------------
__device__ __align__(16) float g_Q[MROWS * DMODEL];   // 32 MB
__device__ __align__(16) float g_K[MROWS * DKV];      // 8 MB
__device__ __align__(16) float g_V[MROWS * DKV];      // 8 MB
__device__ __align__(16) float g_Y[MROWS * DMODEL];   // 32 MB

__device__ __align__(16) bf16 g_xh[MROWS * DMODEL];   // 16 MB
__device__ __align__(16) bf16 g_xl[MROWS * DMODEL];
__device__ __align__(16) bf16 g_yh[MROWS * DMODEL];
__device__ __align__(16) bf16 g_yl[MROWS * DMODEL];

__device__ __align__(16) bf16 g_WqTh[DMODEL * DMODEL]; // [N][K] transposed
__device__ __align__(16) bf16 g_WqTl[DMODEL * DMODEL];
__device__ __align__(16) bf16 g_WkTh[DKV * DMODEL];
__device__ __align__(16) bf16 g_WkTl[DKV * DMODEL];
__device__ __align__(16) bf16 g_WvTh[DKV * DMODEL];
__device__ __align__(16) bf16 g_WvTl[DKV * DMODEL];
__device__ __align__(16) bf16 g_WoTh[DMODEL * DMODEL];
__device__ __align__(16) bf16 g_WoTl[DMODEL * DMODEL];

// ---------------- PTX helpers (compute_100-safe: mma.sync / ldmatrix / cp.async) ---
__device__ __forceinline__ uint32_t smem_u32(const void* p) {
    uint32_t a;
    asm("{ .reg .u64 t; cvta.to.shared.u64 t, %1; cvt.u32.u64 %0, t; }"
        : "=r"(a) : "l"(p));
    return a;
}
__device__ __forceinline__ void cp16(uint32_t dst, const void* src) {
    asm volatile("cp.async.cg.shared.global [%0], [%1], 16;"
                 :: "r"(dst), "l"(src) : "memory");
}
#define CP_COMMIT() asm volatile("cp.async.commit_group;" ::: "memory")
#define CP_WAIT0()  asm volatile("cp.async.wait_group 0;" ::: "memory")

__device__ __forceinline__ void ldm4(uint32_t* r, uint32_t addr) {
    asm volatile("ldmatrix.sync.aligned.m8n8.x4.shared.b16 {%0,%1,%2,%3}, [%4];"
                 : "=r"(r[0]), "=r"(r[1]), "=r"(r[2]), "=r"(r[3]) : "r"(addr));
}
__device__ __forceinline__ void mma16816(float* c, const uint32_t* a, const uint32_t* b) {
    asm volatile(
        "mma.sync.aligned.m16n8k16.row.col.f32.bf16.bf16.f32 "
        "{%0,%1,%2,%3}, {%4,%5,%6,%7}, {%8,%9}, {%0,%1,%2,%3};"
        : "+f"(c[0]), "+f"(c[1]), "+f"(c[2]), "+f"(c[3])
        : "r"(a[0]), "r"(a[1]), "r"(a[2]), "r"(a[3]), "r"(b[0]), "r"(b[1]));
}

// ---------------- split / transpose conversion kernels ----------------
__global__ void split_kernel(const float* __restrict__ s,
                             bf16* __restrict__ h, bf16* __restrict__ l) {
    int i = blockIdx.x * blockDim.x + threadIdx.x;
    float4 v = ((const float4*)s)[i];
    bf16 h0 = __float2bfloat16(v.x); bf16 l0 = __float2bfloat16(v.x - __bfloat162float(h0));
    bf16 h1 = __float2bfloat16(v.y); bf16 l1 = __float2bfloat16(v.y - __bfloat162float(h1));
    bf16 h2 = __float2bfloat16(v.z); bf16 l2 = __float2bfloat16(v.z - __bfloat162float(h2));
    bf16 h3 = __float2bfloat16(v.w); bf16 l3 = __float2bfloat16(v.w - __bfloat162float(h3));
    ((__nv_bfloat162*)h)[2*i]   = __halves2bfloat162(h0, h1);
    ((__nv_bfloat162*)h)[2*i+1] = __halves2bfloat162(h2, h3);
    ((__nv_bfloat162*)l)[2*i]   = __halves2bfloat162(l0, l1);
    ((__nv_bfloat162*)l)[2*i+1] = __halves2bfloat162(l2, l3);
}

// src fp32 [K][N] row-major -> dst bf16 hi/lo [N][K]
__global__ void split_transpose_kernel(const float* __restrict__ src,
                                       bf16* __restrict__ dh, bf16* __restrict__ dl,
                                       int K, int N) {
    __shared__ float t[32][33];
    int n0 = blockIdx.x * 32, k0 = blockIdx.y * 32;
    int tx = threadIdx.x, ty = threadIdx.y;   // 32 x 8
    #pragma unroll
    for (int i = 0; i < 4; i++)
        t[ty + 8*i][tx] = src[(size_t)(k0 + ty + 8*i) * N + n0 + tx];
    __syncthreads();
    #pragma unroll
    for (int i = 0; i < 4; i++) {
        float v = t[tx][ty + 8*i];
        bf16 h = __float2bfloat16(v);
        bf16 l = __float2bfloat16(v - __bfloat162float(h));
        size_t o = (size_t)(n0 + ty + 8*i) * K + k0 + tx;
        dh[o] = h; dl[o] = l;
    }
}

// ---------------- mma.sync split-bf16 GEMM (static smem, no attribute calls) -----
// C[M,N] fp32 = A[M,K] @ B[K,N]; A split (Ah,Al) row-major [M][K]; B split-
// transposed (Bh,Bl) row-major [N][K]. Block 64x64, BK=32, 4 warps (2x2),
// warp tile 32x32. 3 products: Ah*Bh + Al*Bh + Ah*Bl. Double-buffered cp.async.
#define GBK 32
#define PITCH 80                       // 64B data + 16B pad (conflict-free ldmatrix)
#define ARR_BYTES (64 * PITCH)         // 5120
#define BUF_BYTES (4 * ARR_BYTES)      // Ah, Al, Bh, Bl -> 20480
// total static: 2 * 20480 = 40960 B  (<= 48KB default limit, no opt-in needed)

__global__ __launch_bounds__(128, 1) void gemm_mma(
    const bf16* __restrict__ Ah, const bf16* __restrict__ Al,
    const bf16* __restrict__ Bh, const bf16* __restrict__ Bl,
    float* __restrict__ C, int N, int K)
{
    __shared__ __align__(16) char smem[2 * BUF_BYTES];
    const uint32_t sbase = smem_u32(smem);
    const int tid = threadIdx.x, lane = tid & 31, wid = tid >> 5;
    const int warp_m = wid & 1, warp_n = wid >> 1;
    const int m0 = blockIdx.y * 64, n0 = blockIdx.x * 64;
    const int KT = K / GBK;

    const bf16* srcs[4] = { Ah + (size_t)m0 * K, Al + (size_t)m0 * K,
                            Bh + (size_t)n0 * K, Bl + (size_t)n0 * K };

    // per array: 64 rows x 4 chunks of 16B (64B row = GBK*2 bytes) = 256 cp16
    // 128 threads -> 2 per thread (rows +0 and +32)
    const int ld_row = tid >> 2, ld_c = tid & 3;
    auto load_tile = [&](int kt, int b) {
        uint32_t bufb = sbase + b * BUF_BYTES;
        #pragma unroll
        for (int arr = 0; arr < 4; arr++) {
            const bf16* s = srcs[arr] + kt * GBK;
            uint32_t d0 = bufb + arr * ARR_BYTES;
            #pragma unroll
            for (int i = 0; i < 2; i++) {
                int row = ld_row + i * 32;
                cp16(d0 + row * PITCH + ld_c * 16,
                     s + (size_t)row * K + ld_c * 8);
            }
        }
        CP_COMMIT();
    };

    float acc[2][4][4];
    #pragma unroll
    for (int mt = 0; mt < 2; mt++)
        #pragma unroll
        for (int nt = 0; nt < 4; nt++)
            #pragma unroll
            for (int i = 0; i < 4; i++) acc[mt][nt][i] = 0.f;

    // ldmatrix lane addressing
    const int a_row  = warp_m * 32 + (lane & 15);
    const int a_koff = (lane >> 4) << 3;
    const int quad   = lane >> 3;
    const int b_row  = warp_n * 32 + ((quad >> 1) << 3) + (lane & 7);
    const int b_koff = (quad & 1) << 3;

    load_tile(0, 0);

    for (int kt = 0; kt < KT; kt++) {
        const int cur = kt & 1;
        CP_WAIT0();
        __syncthreads();
        if (kt + 1 < KT) load_tile(kt + 1, cur ^ 1);

        const uint32_t bufc = sbase + cur * BUF_BYTES;
        #pragma unroll
        for (int ks = 0; ks < 2; ks++) {
            uint32_t ah[2][4], al[2][4], bh[2][4], bl[2][4];
            #pragma unroll
            for (int mt = 0; mt < 2; mt++) {
                uint32_t ra = (a_row + mt * 16) * PITCH + (ks * 16 + a_koff) * 2;
                ldm4(ah[mt], bufc + 0 * ARR_BYTES + ra);
                ldm4(al[mt], bufc + 1 * ARR_BYTES + ra);
            }
            #pragma unroll
            for (int nt = 0; nt < 2; nt++) {
                uint32_t rb = (b_row + nt * 16) * PITCH + (ks * 16 + b_koff) * 2;
                ldm4(bh[nt], bufc + 2 * ARR_BYTES + rb);
                ldm4(bl[nt], bufc + 3 * ARR_BYTES + rb);
            }
            #pragma unroll
            for (int mt = 0; mt < 2; mt++)
                #pragma unroll
                for (int n8 = 0; n8 < 4; n8++) {
                    const uint32_t* bhp = &bh[n8 >> 1][(n8 & 1) * 2];
                    const uint32_t* blp = &bl[n8 >> 1][(n8 & 1) * 2];
                    mma16816(acc[mt][n8], ah[mt], bhp);
                    mma16816(acc[mt][n8], al[mt], bhp);
                    mma16816(acc[mt][n8], ah[mt], blp);
                }
        }
        __syncthreads();
    }

    // epilogue: c0,c1 -> (m, n..n+1); c2,c3 -> (m+8, n..n+1)
    #pragma unroll
    for (int mt = 0; mt < 2; mt++) {
        int r = m0 + warp_m * 32 + mt * 16 + (lane >> 2);
        int cbase = n0 + warp_n * 32 + (lane & 3) * 2;
        #pragma unroll
        for (int n8 = 0; n8 < 4; n8++) {
            int c = cbase + n8 * 8;
            *(float2*)&C[(size_t)r * N + c]       = make_float2(acc[mt][n8][0], acc[mt][n8][1]);
            *(float2*)&C[(size_t)(r + 8) * N + c] = make_float2(acc[mt][n8][2], acc[mt][n8][3]);
        }
    }
}

// ---------------- fused RMSNorm + RoPE (in place), one warp per (token, head) ----
__global__ void rmsnorm_rope_kernel(
    float* __restrict__ X, const float* __restrict__ w,
    const float* __restrict__ cosp, const float* __restrict__ sinp,
    int heads)
{
    int gw   = (blockIdx.x * blockDim.x + threadIdx.x) >> 5;
    int lane = threadIdx.x & 31;
    int token = gw / heads;
    int h     = gw - token * heads;
    int t     = token & (SEQ - 1);

    float* row = X + ((size_t)token * heads + h) * HDIM;
    float x1 = row[lane];
    float x2 = row[lane + 32];

    float ss = x1 * x1 + x2 * x2;
    #pragma unroll
    for (int o = 16; o; o >>= 1) ss += __shfl_xor_sync(0xffffffffu, ss, o);
    float r = rsqrtf(ss * (1.f / 64.f) + EPSV);

    x1 *= r * w[lane];
    x2 *= r * w[lane + 32];

    float c = cosp[t * 32 + lane];
    float s = sinp[t * 32 + lane];
    row[lane]      = x1 * c - x2 * s;
    row[lane + 32] = x1 * s + x2 * c;
}

// ---------------- flash attention: 1 thread = 1 q row, KV tiles of 32 ------------
#define KVT 32

__global__ __launch_bounds__(128, 1) void flash_kernel(
    const float* __restrict__ Q, const float* __restrict__ K,
    const float* __restrict__ V, float* __restrict__ Y)
{
    __shared__ float4 Ks[KVT][16];
    __shared__ float4 Vs[KVT][16];

    const int qb  = blockIdx.x * 128;
    const int h   = blockIdx.y;
    const int b   = blockIdx.z;
    const int kvh = h >> 2;
    const int t   = qb + threadIdx.x;
    const int tid = threadIdx.x;

    const float* qrow = Q + ((size_t)(b * SEQ + t)) * DMODEL + h * HDIM;
    float4 q4[16];
    #pragma unroll
    for (int c = 0; c < 16; c++) {
        float4 v = *(const float4*)&qrow[c * 4];
        v.x *= ATT_SCALE; v.y *= ATT_SCALE; v.z *= ATT_SCALE; v.w *= ATT_SCALE;
        q4[c] = v;
    }

    float4 o4[16];
    #pragma unroll
    for (int c = 0; c < 16; c++) o4[c] = make_float4(0.f, 0.f, 0.f, 0.f);
    float m = -1e30f, l = 0.f;

    const int ntiles = (qb + 128) / KVT;
    for (int tt = 0; tt < ntiles; tt++) {
        const int jt = tt * KVT;
        #pragma unroll
        for (int i = 0; i < 4; i++) {
            int lin = tid + i * 128;
            int j   = lin >> 4;
            int c4  = lin & 15;
            size_t base = ((size_t)(b * SEQ + jt + j)) * DKV + kvh * HDIM + c4 * 4;
            Ks[j][c4] = *(const float4*)&K[base];
            Vs[j][c4] = *(const float4*)&V[base];
        }
        __syncthreads();

        if (t >= jt) {
            const int lim = t - jt;
            float s[KVT];
            float mt = -1e30f;
            #pragma unroll
            for (int j = 0; j < KVT; j++) {
                float a = 0.f;
                #pragma unroll
                for (int c = 0; c < 16; c++) {
                    float4 kk4 = Ks[j][c];
                    a = fmaf(q4[c].x, kk4.x, a);
                    a = fmaf(q4[c].y, kk4.y, a);
                    a = fmaf(q4[c].z, kk4.z, a);
                    a = fmaf(q4[c].w, kk4.w, a);
                }
                a = (j <= lim) ? a : -1e30f;
                s[j] = a;
                mt = fmaxf(mt, a);
            }
            float mn   = fmaxf(m, mt);
            float cfac = __expf(m - mn);
            l *= cfac;
            #pragma unroll
            for (int c = 0; c < 16; c++) {
                o4[c].x *= cfac; o4[c].y *= cfac; o4[c].z *= cfac; o4[c].w *= cfac;
            }
            #pragma unroll
            for (int j = 0; j < KVT; j++) {
                float p = __expf(s[j] - mn);
                l += p;
                #pragma unroll
                for (int c = 0; c < 16; c++) {
                    float4 vv = Vs[j][c];
                    o4[c].x = fmaf(p, vv.x, o4[c].x);
                    o4[c].y = fmaf(p, vv.y, o4[c].y);
                    o4[c].z = fmaf(p, vv.z, o4[c].z);
                    o4[c].w = fmaf(p, vv.w, o4[c].w);
                }
            }
            m = mn;
        }
        __syncthreads();
    }

    float inv = 1.f / l;
    float* yrow = Y + ((size_t)(b * SEQ + t)) * DMODEL + h * HDIM;
    #pragma unroll
    for (int c = 0; c < 16; c++) {
        float4 v = o4[c];
        v.x *= inv; v.y *= inv; v.z *= inv; v.w *= inv;
        *(float4*)&yrow[c * 4] = v;
    }
}

// ---------------- launch ----------------
extern "C" void kernel_launch(void* const* d_in, const int* in_sizes, int n_in,
                              void* d_out, int out_size)
{
    const float* x    = (const float*)d_in[0];
    const float* Wq   = (const float*)d_in[1];
    const float* Wk   = (const float*)d_in[2];
    const float* Wv   = (const float*)d_in[3];
    const float* Wo   = (const float*)d_in[4];
    const float* qw   = (const float*)d_in[5];
    const float* kw   = (const float*)d_in[6];
    const float* cosp = (const float*)d_in[7];
    const float* sinp = (const float*)d_in[8];
    float* out = (float*)d_out;

    float *qp, *kp, *vp, *yp;
    bf16 *xh, *xl, *yh, *yl;
    bf16 *wqh, *wql, *wkh, *wkl, *wvh, *wvl, *woh, *wol;
    cudaGetSymbolAddress((void**)&qp, g_Q);
    cudaGetSymbolAddress((void**)&kp, g_K);
    cudaGetSymbolAddress((void**)&vp, g_V);
    cudaGetSymbolAddress((void**)&yp, g_Y);
    cudaGetSymbolAddress((void**)&xh, g_xh);
    cudaGetSymbolAddress((void**)&xl, g_xl);
    cudaGetSymbolAddress((void**)&yh, g_yh);
    cudaGetSymbolAddress((void**)&yl, g_yl);
    cudaGetSymbolAddress((void**)&wqh, g_WqTh);
    cudaGetSymbolAddress((void**)&wql, g_WqTl);
    cudaGetSymbolAddress((void**)&wkh, g_WkTh);
    cudaGetSymbolAddress((void**)&wkl, g_WkTl);
    cudaGetSymbolAddress((void**)&wvh, g_WvTh);
    cudaGetSymbolAddress((void**)&wvl, g_WvTl);
    cudaGetSymbolAddress((void**)&woh, g_WoTh);
    cudaGetSymbolAddress((void**)&wol, g_WoTl);

    // input + weight conversion (split bf16; weights transposed to [N][K])
    split_kernel<<<(MROWS * DMODEL / 4) / 256, 256>>>(x, xh, xl);
    split_transpose_kernel<<<dim3(DMODEL/32, DMODEL/32), dim3(32,8)>>>(Wq, wqh, wql, DMODEL, DMODEL);
    split_transpose_kernel<<<dim3(DKV/32,    DMODEL/32), dim3(32,8)>>>(Wk, wkh, wkl, DMODEL, DKV);
    split_transpose_kernel<<<dim3(DKV/32,    DMODEL/32), dim3(32,8)>>>(Wv, wvh, wvl, DMODEL, DKV);
    split_transpose_kernel<<<dim3(DMODEL/32, DMODEL/32), dim3(32,8)>>>(Wo, woh, wol, DMODEL, DMODEL);

    // projections on tensor cores (mma.sync bf16, 3-product split)
    gemm_mma<<<dim3(DMODEL/64, MROWS/64), 128>>>(xh, xl, wqh, wql, qp, DMODEL, DMODEL);
    gemm_mma<<<dim3(DKV/64,    MROWS/64), 128>>>(xh, xl, wkh, wkl, kp, DKV,    DMODEL);
    gemm_mma<<<dim3(DKV/64,    MROWS/64), 128>>>(xh, xl, wvh, wvl, vp, DKV,    DMODEL);

    // rmsnorm + rope (in place)
    rmsnorm_rope_kernel<<<(MROWS * NHEAD) / 8, 256>>>(qp, qw, cosp, sinp, NHEAD);
    rmsnorm_rope_kernel<<<(MROWS * NKV)   / 8, 256>>>(kp, kw, cosp, sinp, NKV);

    // attention
    flash_kernel<<<dim3(SEQ / 128, NHEAD, BATCH), 128>>>(qp, kp, vp, yp);

    // output projection
    split_kernel<<<(MROWS * DMODEL / 4) / 256, 256>>>(yp, yh, yl);
    gemm_mma<<<dim3(DMODEL/64, MROWS/64), 128>>>(yh, yl, woh, wol, out, DMODEL, DMODEL);
}

// round 9
// speedup vs baseline: 2.9302x; 1.7678x over previous
#include <cuda_runtime.h>
#include <cuda_bf16.h>
#include <cstdint>

// ---------------- problem constants ----------------
#define BATCH   4
#define SEQ     1024
#define DMODEL  2048
#define NHEAD   32
#define NKV     8
#define HDIM    64
#define MROWS   (BATCH*SEQ)          // 4096
#define DKV     (NKV*HDIM)           // 512
#define EPSV    1e-6f
#define ATT_SCALE 0.125f

typedef __nv_bfloat16 bf16;

// ---------------- scratch (device globals; no allocs allowed) ----------------
__device__ __align__(16) float g_Q[MROWS * DMODEL];
__device__ __align__(16) float g_K[MROWS * DKV];
__device__ __align__(16) float g_V[MROWS * DKV];
__device__ __align__(16) float g_Y[MROWS * DMODEL];

__device__ __align__(16) bf16 g_xh[MROWS * DMODEL];
__device__ __align__(16) bf16 g_xl[MROWS * DMODEL];
__device__ __align__(16) bf16 g_yh[MROWS * DMODEL];
__device__ __align__(16) bf16 g_yl[MROWS * DMODEL];

__device__ __align__(16) bf16 g_WqTh[DMODEL * DMODEL];
__device__ __align__(16) bf16 g_WqTl[DMODEL * DMODEL];
__device__ __align__(16) bf16 g_WkTh[DKV * DMODEL];
__device__ __align__(16) bf16 g_WkTl[DKV * DMODEL];
__device__ __align__(16) bf16 g_WvTh[DKV * DMODEL];
__device__ __align__(16) bf16 g_WvTl[DKV * DMODEL];
__device__ __align__(16) bf16 g_WoTh[DMODEL * DMODEL];
__device__ __align__(16) bf16 g_WoTl[DMODEL * DMODEL];

// head-major attention operands (bf16 hi/lo)
__device__ __align__(16) bf16 g_Qah[MROWS * DMODEL];
__device__ __align__(16) bf16 g_Qal[MROWS * DMODEL];
__device__ __align__(16) bf16 g_Kah[MROWS * DKV];
__device__ __align__(16) bf16 g_Kal[MROWS * DKV];
__device__ __align__(16) bf16 g_Vah[MROWS * DKV];
__device__ __align__(16) bf16 g_Val[MROWS * DKV];

// ---------------- PTX helpers ----------------
__device__ __forceinline__ uint32_t smem_u32(const void* p) {
    uint32_t a;
    asm("{ .reg .u64 t; cvta.to.shared.u64 t, %1; cvt.u32.u64 %0, t; }"
        : "=r"(a) : "l"(p));
    return a;
}
__device__ __forceinline__ void cp16(uint32_t dst, const void* src) {
    asm volatile("cp.async.cg.shared.global [%0], [%1], 16;"
                 :: "r"(dst), "l"(src) : "memory");
}
#define CP_COMMIT() asm volatile("cp.async.commit_group;" ::: "memory")
#define CP_WAIT0()  asm volatile("cp.async.wait_group 0;" ::: "memory")

__device__ __forceinline__ void ldm4(uint32_t* r, uint32_t addr) {
    asm volatile("ldmatrix.sync.aligned.m8n8.x4.shared.b16 {%0,%1,%2,%3}, [%4];"
                 : "=r"(r[0]), "=r"(r[1]), "=r"(r[2]), "=r"(r[3]) : "r"(addr));
}
__device__ __forceinline__ void ldm4t(uint32_t* r, uint32_t addr) {
    asm volatile("ldmatrix.sync.aligned.m8n8.x4.trans.shared.b16 {%0,%1,%2,%3}, [%4];"
                 : "=r"(r[0]), "=r"(r[1]), "=r"(r[2]), "=r"(r[3]) : "r"(addr));
}
__device__ __forceinline__ void mma16816(float* c, const uint32_t* a, const uint32_t* b) {
    asm volatile(
        "mma.sync.aligned.m16n8k16.row.col.f32.bf16.bf16.f32 "
        "{%0,%1,%2,%3}, {%4,%5,%6,%7}, {%8,%9}, {%0,%1,%2,%3};"
        : "+f"(c[0]), "+f"(c[1]), "+f"(c[2]), "+f"(c[3])
        : "r"(a[0]), "r"(a[1]), "r"(a[2]), "r"(a[3]), "r"(b[0]), "r"(b[1]));
}
__device__ __forceinline__ uint32_t packbf(bf16 lo, bf16 hi) {
    __nv_bfloat162 v = __halves2bfloat162(lo, hi);
    return *(uint32_t*)&v;
}

// ---------------- split / transpose conversion kernels ----------------
__global__ void split_kernel(const float* __restrict__ s,
                             bf16* __restrict__ h, bf16* __restrict__ l) {
    int i = blockIdx.x * blockDim.x + threadIdx.x;
    float4 v = ((const float4*)s)[i];
    bf16 h0 = __float2bfloat16(v.x); bf16 l0 = __float2bfloat16(v.x - __bfloat162float(h0));
    bf16 h1 = __float2bfloat16(v.y); bf16 l1 = __float2bfloat16(v.y - __bfloat162float(h1));
    bf16 h2 = __float2bfloat16(v.z); bf16 l2 = __float2bfloat16(v.z - __bfloat162float(h2));
    bf16 h3 = __float2bfloat16(v.w); bf16 l3 = __float2bfloat16(v.w - __bfloat162float(h3));
    ((__nv_bfloat162*)h)[2*i]   = __halves2bfloat162(h0, h1);
    ((__nv_bfloat162*)h)[2*i+1] = __halves2bfloat162(h2, h3);
    ((__nv_bfloat162*)l)[2*i]   = __halves2bfloat162(l0, l1);
    ((__nv_bfloat162*)l)[2*i+1] = __halves2bfloat162(l2, l3);
}

__global__ void split_transpose_kernel(const float* __restrict__ src,
                                       bf16* __restrict__ dh, bf16* __restrict__ dl,
                                       int K, int N) {
    __shared__ float t[32][33];
    int n0 = blockIdx.x * 32, k0 = blockIdx.y * 32;
    int tx = threadIdx.x, ty = threadIdx.y;
    #pragma unroll
    for (int i = 0; i < 4; i++)
        t[ty + 8*i][tx] = src[(size_t)(k0 + ty + 8*i) * N + n0 + tx];
    __syncthreads();
    #pragma unroll
    for (int i = 0; i < 4; i++) {
        float v = t[tx][ty + 8*i];
        bf16 h = __float2bfloat16(v);
        bf16 l = __float2bfloat16(v - __bfloat162float(h));
        size_t o = (size_t)(n0 + ty + 8*i) * K + k0 + tx;
        dh[o] = h; dl[o] = l;
    }
}

// ---------------- mma.sync split-bf16 GEMM (unchanged from passing R7) ----------
#define GBK 32
#define PITCH 80
#define ARR_BYTES (64 * PITCH)
#define BUF_BYTES (4 * ARR_BYTES)

__global__ __launch_bounds__(128, 1) void gemm_mma(
    const bf16* __restrict__ Ah, const bf16* __restrict__ Al,
    const bf16* __restrict__ Bh, const bf16* __restrict__ Bl,
    float* __restrict__ C, int N, int K)
{
    __shared__ __align__(16) char smem[2 * BUF_BYTES];
    const uint32_t sbase = smem_u32(smem);
    const int tid = threadIdx.x, lane = tid & 31, wid = tid >> 5;
    const int warp_m = wid & 1, warp_n = wid >> 1;
    const int m0 = blockIdx.y * 64, n0 = blockIdx.x * 64;
    const int KT = K / GBK;

    const bf16* srcs[4] = { Ah + (size_t)m0 * K, Al + (size_t)m0 * K,
                            Bh + (size_t)n0 * K, Bl + (size_t)n0 * K };

    const int ld_row = tid >> 2, ld_c = tid & 3;
    auto load_tile = [&](int kt, int b) {
        uint32_t bufb = sbase + b * BUF_BYTES;
        #pragma unroll
        for (int arr = 0; arr < 4; arr++) {
            const bf16* s = srcs[arr] + kt * GBK;
            uint32_t d0 = bufb + arr * ARR_BYTES;
            #pragma unroll
            for (int i = 0; i < 2; i++) {
                int row = ld_row + i * 32;
                cp16(d0 + row * PITCH + ld_c * 16,
                     s + (size_t)row * K + ld_c * 8);
            }
        }
        CP_COMMIT();
    };

    float acc[2][4][4];
    #pragma unroll
    for (int mt = 0; mt < 2; mt++)
        #pragma unroll
        for (int nt = 0; nt < 4; nt++)
            #pragma unroll
            for (int i = 0; i < 4; i++) acc[mt][nt][i] = 0.f;

    const int a_row  = warp_m * 32 + (lane & 15);
    const int a_koff = (lane >> 4) << 3;
    const int quad   = lane >> 3;
    const int b_row  = warp_n * 32 + ((quad >> 1) << 3) + (lane & 7);
    const int b_koff = (quad & 1) << 3;

    load_tile(0, 0);

    for (int kt = 0; kt < KT; kt++) {
        const int cur = kt & 1;
        CP_WAIT0();
        __syncthreads();
        if (kt + 1 < KT) load_tile(kt + 1, cur ^ 1);

        const uint32_t bufc = sbase + cur * BUF_BYTES;
        #pragma unroll
        for (int ks = 0; ks < 2; ks++) {
            uint32_t ah[2][4], al[2][4], bh[2][4], bl[2][4];
            #pragma unroll
            for (int mt = 0; mt < 2; mt++) {
                uint32_t ra = (a_row + mt * 16) * PITCH + (ks * 16 + a_koff) * 2;
                ldm4(ah[mt], bufc + 0 * ARR_BYTES + ra);
                ldm4(al[mt], bufc + 1 * ARR_BYTES + ra);
            }
            #pragma unroll
            for (int nt = 0; nt < 2; nt++) {
                uint32_t rb = (b_row + nt * 16) * PITCH + (ks * 16 + b_koff) * 2;
                ldm4(bh[nt], bufc + 2 * ARR_BYTES + rb);
                ldm4(bl[nt], bufc + 3 * ARR_BYTES + rb);
            }
            #pragma unroll
            for (int mt = 0; mt < 2; mt++)
                #pragma unroll
                for (int n8 = 0; n8 < 4; n8++) {
                    const uint32_t* bhp = &bh[n8 >> 1][(n8 & 1) * 2];
                    const uint32_t* blp = &bl[n8 >> 1][(n8 & 1) * 2];
                    mma16816(acc[mt][n8], ah[mt], bhp);
                    mma16816(acc[mt][n8], al[mt], bhp);
                    mma16816(acc[mt][n8], ah[mt], blp);
                }
        }
        __syncthreads();
    }

    #pragma unroll
    for (int mt = 0; mt < 2; mt++) {
        int r = m0 + warp_m * 32 + mt * 16 + (lane >> 2);
        int cbase = n0 + warp_n * 32 + (lane & 3) * 2;
        #pragma unroll
        for (int n8 = 0; n8 < 4; n8++) {
            int c = cbase + n8 * 8;
            *(float2*)&C[(size_t)r * N + c]       = make_float2(acc[mt][n8][0], acc[mt][n8][1]);
            *(float2*)&C[(size_t)(r + 8) * N + c] = make_float2(acc[mt][n8][2], acc[mt][n8][3]);
        }
    }
}

// ---------------- rmsnorm + rope + hi/lo split -> head-major bf16 ---------------
// X fp32 token-major [token][heads*64] -> outH/outL bf16 [(b*heads+h)*SEQ+t][64]
__global__ void rmsnorm_rope_split_kernel(
    const float* __restrict__ X, const float* __restrict__ w,
    const float* __restrict__ cosp, const float* __restrict__ sinp,
    int heads, float scale, bf16* __restrict__ outH, bf16* __restrict__ outL)
{
    int gw   = (blockIdx.x * blockDim.x + threadIdx.x) >> 5;
    int lane = threadIdx.x & 31;
    int token = gw / heads;
    int h     = gw - token * heads;
    int t     = token & (SEQ - 1);
    int b     = token >> 10;

    const float* row = X + ((size_t)token * heads + h) * HDIM;
    float x1 = row[lane];
    float x2 = row[lane + 32];

    float ss = x1 * x1 + x2 * x2;
    #pragma unroll
    for (int o = 16; o; o >>= 1) ss += __shfl_xor_sync(0xffffffffu, ss, o);
    float r = rsqrtf(ss * (1.f / 64.f) + EPSV);

    x1 *= r * w[lane];
    x2 *= r * w[lane + 32];

    float c = cosp[t * 32 + lane];
    float s = sinp[t * 32 + lane];
    float v1 = (x1 * c - x2 * s) * scale;
    float v2 = (x1 * s + x2 * c) * scale;

    size_t o = ((size_t)(b * heads + h) * SEQ + t) * HDIM;
    bf16 h1 = __float2bfloat16(v1); outH[o + lane]      = h1;
    outL[o + lane]      = __float2bfloat16(v1 - __bfloat162float(h1));
    bf16 h2 = __float2bfloat16(v2); outH[o + lane + 32] = h2;
    outL[o + lane + 32] = __float2bfloat16(v2 - __bfloat162float(h2));
}

// V fp32 token-major [token][kvh*64] -> head-major hi/lo
__global__ void split_v_kernel(const float* __restrict__ X,
                               bf16* __restrict__ outH, bf16* __restrict__ outL)
{
    int gw   = (blockIdx.x * blockDim.x + threadIdx.x) >> 5;
    int lane = threadIdx.x & 31;
    int token = gw / NKV;
    int kvh   = gw - token * NKV;
    int t     = token & (SEQ - 1);
    int b     = token >> 10;

    const float* row = X + (size_t)token * DKV + kvh * HDIM;
    float v1 = row[lane], v2 = row[lane + 32];
    size_t o = ((size_t)(b * NKV + kvh) * SEQ + t) * HDIM;
    bf16 h1 = __float2bfloat16(v1); outH[o + lane]      = h1;
    outL[o + lane]      = __float2bfloat16(v1 - __bfloat162float(h1));
    bf16 h2 = __float2bfloat16(v2); outH[o + lane + 32] = h2;
    outL[o + lane + 32] = __float2bfloat16(v2 - __bfloat162float(h2));
}

// ---------------- tensor-core flash attention ----------------
// grid (SEQ/64, NHEAD, BATCH), 128 threads (4 warps x 16 q-rows).
#define PITCHA 144                     // 128B data + 16B pad (conflict-free)
#define FARR   (64 * PITCHA)           // 9216; Kh,Kl,Vh,Vl -> 36864B static

__global__ __launch_bounds__(128, 1) void flash_mma(
    const bf16* __restrict__ Qh, const bf16* __restrict__ Ql,
    const bf16* __restrict__ Kh, const bf16* __restrict__ Kl,
    const bf16* __restrict__ Vh, const bf16* __restrict__ Vl,
    float* __restrict__ Y)
{
    __shared__ __align__(16) char sm[4 * FARR];
    const uint32_t sb = smem_u32(sm);
    const int tid = threadIdx.x, lane = tid & 31, wid = tid >> 5;
    const int qt = blockIdx.x, h = blockIdx.y, b = blockIdx.z, kvh = h >> 2;
    const int qbase = qt * 64;

    const bf16* qh_g = Qh + ((size_t)(b * NHEAD + h) * SEQ + qbase) * HDIM;
    const bf16* ql_g = Ql + ((size_t)(b * NHEAD + h) * SEQ + qbase) * HDIM;
    const bf16* kh_g = Kh + ((size_t)(b * NKV + kvh) * SEQ) * HDIM;
    const bf16* kl_g = Kl + ((size_t)(b * NKV + kvh) * SEQ) * HDIM;
    const bf16* vh_g = Vh + ((size_t)(b * NKV + kvh) * SEQ) * HDIM;
    const bf16* vl_g = Vl + ((size_t)(b * NKV + kvh) * SEQ) * HDIM;

    // ---- stage Q tile into buffers 0/1, extract A-fragments to registers ----
    #pragma unroll
    for (int i = 0; i < 4; i++) {
        int id = tid + i * 128;            // 0..511
        int row = id >> 3, c = id & 7;
        cp16(sb + 0 * FARR + row * PITCHA + c * 16, qh_g + (size_t)row * HDIM + c * 8);
        cp16(sb + 1 * FARR + row * PITCHA + c * 16, ql_g + (size_t)row * HDIM + c * 8);
    }
    CP_COMMIT(); CP_WAIT0();
    __syncthreads();

    uint32_t qfh[4][4], qfl[4][4];
    const int a_row  = wid * 16 + (lane & 15);
    const int a_koff = (lane >> 4) << 3;
    #pragma unroll
    for (int ks = 0; ks < 4; ks++) {
        uint32_t ra = a_row * PITCHA + (ks * 16 + a_koff) * 2;
        ldm4(qfh[ks], sb + 0 * FARR + ra);
        ldm4(qfl[ks], sb + 1 * FARR + ra);
    }
    __syncthreads();

    // ---- state ----
    float s[8][4], o[8][4];
    #pragma unroll
    for (int j = 0; j < 8; j++)
        #pragma unroll
        for (int i = 0; i < 4; i++) o[j][i] = 0.f;
    float m0r = -1e30f, m1r = -1e30f, l0r = 0.f, l1r = 0.f;

    const int quad   = lane >> 3;
    const int kb_row = ((quad >> 1) << 3) + (lane & 7);
    const int kb_off = (quad & 1) << 3;
    const int v_rsub = ((lane >> 3) & 1) * 8 + (lane & 7);
    const int v_csub = (lane >> 4) << 3;
    const int r0 = qbase + wid * 16 + (lane >> 2);

    for (int jt = 0; jt <= qbase; jt += 64) {
        __syncthreads();
        // load K/V hi/lo tiles
        const bf16* gs[4] = { kh_g + (size_t)jt * HDIM, kl_g + (size_t)jt * HDIM,
                              vh_g + (size_t)jt * HDIM, vl_g + (size_t)jt * HDIM };
        #pragma unroll
        for (int arr = 0; arr < 4; arr++) {
            #pragma unroll
            for (int i = 0; i < 4; i++) {
                int id = tid + i * 128;
                int row = id >> 3, c = id & 7;
                cp16(sb + arr * FARR + row * PITCHA + c * 16,
                     gs[arr] + (size_t)row * HDIM + c * 8);
            }
        }
        CP_COMMIT(); CP_WAIT0();
        __syncthreads();

        // ---- S = Q K^T (3-product split) ----
        #pragma unroll
        for (int j = 0; j < 8; j++)
            #pragma unroll
            for (int i = 0; i < 4; i++) s[j][i] = 0.f;
        #pragma unroll
        for (int ks = 0; ks < 4; ks++) {
            uint32_t kh4[4][4], kl4[4][4];
            #pragma unroll
            for (int nt = 0; nt < 4; nt++) {
                uint32_t rb = (nt * 16 + kb_row) * PITCHA + (ks * 16 + kb_off) * 2;
                ldm4(kh4[nt], sb + 0 * FARR + rb);
                ldm4(kl4[nt], sb + 1 * FARR + rb);
            }
            #pragma unroll
            for (int n8 = 0; n8 < 8; n8++) {
                const uint32_t* bh2 = &kh4[n8 >> 1][(n8 & 1) * 2];
                const uint32_t* bl2 = &kl4[n8 >> 1][(n8 & 1) * 2];
                mma16816(s[n8], qfh[ks], bh2);
                mma16816(s[n8], qfl[ks], bh2);
                mma16816(s[n8], qfh[ks], bl2);
            }
        }

        // causal mask (diagonal tile only)
        if (jt == qbase) {
            #pragma unroll
            for (int j = 0; j < 8; j++) {
                int c = jt + j * 8 + (lane & 3) * 2;
                if (c     > r0)     s[j][0] = -1e30f;
                if (c + 1 > r0)     s[j][1] = -1e30f;
                if (c     > r0 + 8) s[j][2] = -1e30f;
                if (c + 1 > r0 + 8) s[j][3] = -1e30f;
            }
        }

        // ---- online softmax ----
        float mt0 = -1e30f, mt1 = -1e30f;
        #pragma unroll
        for (int j = 0; j < 8; j++) {
            mt0 = fmaxf(mt0, fmaxf(s[j][0], s[j][1]));
            mt1 = fmaxf(mt1, fmaxf(s[j][2], s[j][3]));
        }
        mt0 = fmaxf(mt0, __shfl_xor_sync(0xffffffffu, mt0, 1));
        mt0 = fmaxf(mt0, __shfl_xor_sync(0xffffffffu, mt0, 2));
        mt1 = fmaxf(mt1, __shfl_xor_sync(0xffffffffu, mt1, 1));
        mt1 = fmaxf(mt1, __shfl_xor_sync(0xffffffffu, mt1, 2));

        float mn0 = fmaxf(m0r, mt0), mn1 = fmaxf(m1r, mt1);
        float cf0 = __expf(m0r - mn0), cf1 = __expf(m1r - mn1);
        l0r *= cf0; l1r *= cf1;
        #pragma unroll
        for (int j = 0; j < 8; j++) {
            o[j][0] *= cf0; o[j][1] *= cf0; o[j][2] *= cf1; o[j][3] *= cf1;
        }

        uint32_t ph01[8], ph23[8], pl01[8], pl23[8];
        #pragma unroll
        for (int j = 0; j < 8; j++) {
            float p0 = __expf(s[j][0] - mn0), p1 = __expf(s[j][1] - mn0);
            float p2 = __expf(s[j][2] - mn1), p3 = __expf(s[j][3] - mn1);
            l0r += p0 + p1; l1r += p2 + p3;
            bf16 h0 = __float2bfloat16(p0), h1 = __float2bfloat16(p1);
            bf16 h2 = __float2bfloat16(p2), h3 = __float2bfloat16(p3);
            ph01[j] = packbf(h0, h1);
            ph23[j] = packbf(h2, h3);
            pl01[j] = packbf(__float2bfloat16(p0 - __bfloat162float(h0)),
                             __float2bfloat16(p1 - __bfloat162float(h1)));
            pl23[j] = packbf(__float2bfloat16(p2 - __bfloat162float(h2)),
                             __float2bfloat16(p3 - __bfloat162float(h3)));
        }
        m0r = mn0; m1r = mn1;

        // ---- O += P V (3-product split), V via ldmatrix.trans ----
        #pragma unroll
        for (int ks = 0; ks < 4; ks++) {
            uint32_t aph[4] = { ph01[2*ks], ph23[2*ks], ph01[2*ks+1], ph23[2*ks+1] };
            uint32_t apl[4] = { pl01[2*ks], pl23[2*ks], pl01[2*ks+1], pl23[2*ks+1] };
            uint32_t vh4[4][4], vl4[4][4];
            #pragma unroll
            for (int nt = 0; nt < 4; nt++) {
                uint32_t rv = (ks * 16 + v_rsub) * PITCHA + (nt * 16 + v_csub) * 2;
                ldm4t(vh4[nt], sb + 2 * FARR + rv);
                ldm4t(vl4[nt], sb + 3 * FARR + rv);
            }
            #pragma unroll
            for (int d8 = 0; d8 < 8; d8++) {
                const uint32_t* bh2 = &vh4[d8 >> 1][(d8 & 1) * 2];
                const uint32_t* bl2 = &vl4[d8 >> 1][(d8 & 1) * 2];
                mma16816(o[d8], aph, bh2);
                mma16816(o[d8], aph, bl2);
                mma16816(o[d8], apl, bh2);
            }
        }
    }

    // final normalize + write (token-major for Wo gemm)
    l0r += __shfl_xor_sync(0xffffffffu, l0r, 1);
    l0r += __shfl_xor_sync(0xffffffffu, l0r, 2);
    l1r += __shfl_xor_sync(0xffffffffu, l1r, 1);
    l1r += __shfl_xor_sync(0xffffffffu, l1r, 2);
    float inv0 = 1.f / l0r, inv1 = 1.f / l1r;

    size_t t0 = (size_t)(b * SEQ + r0) * DMODEL + h * HDIM;
    size_t t1 = (size_t)(b * SEQ + r0 + 8) * DMODEL + h * HDIM;
    #pragma unroll
    for (int j = 0; j < 8; j++) {
        int c = j * 8 + (lane & 3) * 2;
        *(float2*)&Y[t0 + c] = make_float2(o[j][0] * inv0, o[j][1] * inv0);
        *(float2*)&Y[t1 + c] = make_float2(o[j][2] * inv1, o[j][3] * inv1);
    }
}

// ---------------- launch ----------------
extern "C" void kernel_launch(void* const* d_in, const int* in_sizes, int n_in,
                              void* d_out, int out_size)
{
    const float* x    = (const float*)d_in[0];
    const float* Wq   = (const float*)d_in[1];
    const float* Wk   = (const float*)d_in[2];
    const float* Wv   = (const float*)d_in[3];
    const float* Wo   = (const float*)d_in[4];
    const float* qw   = (const float*)d_in[5];
    const float* kw   = (const float*)d_in[6];
    const float* cosp = (const float*)d_in[7];
    const float* sinp = (const float*)d_in[8];
    float* out = (float*)d_out;

    float *qp, *kp, *vp, *yp;
    bf16 *xh, *xl, *yh, *yl;
    bf16 *wqh, *wql, *wkh, *wkl, *wvh, *wvl, *woh, *wol;
    bf16 *qah, *qal, *kah, *kal, *vah, *val;
    cudaGetSymbolAddress((void**)&qp, g_Q);
    cudaGetSymbolAddress((void**)&kp, g_K);
    cudaGetSymbolAddress((void**)&vp, g_V);
    cudaGetSymbolAddress((void**)&yp, g_Y);
    cudaGetSymbolAddress((void**)&xh, g_xh);
    cudaGetSymbolAddress((void**)&xl, g_xl);
    cudaGetSymbolAddress((void**)&yh, g_yh);
    cudaGetSymbolAddress((void**)&yl, g_yl);
    cudaGetSymbolAddress((void**)&wqh, g_WqTh);
    cudaGetSymbolAddress((void**)&wql, g_WqTl);
    cudaGetSymbolAddress((void**)&wkh, g_WkTh);
    cudaGetSymbolAddress((void**)&wkl, g_WkTl);
    cudaGetSymbolAddress((void**)&wvh, g_WvTh);
    cudaGetSymbolAddress((void**)&wvl, g_WvTl);
    cudaGetSymbolAddress((void**)&woh, g_WoTh);
    cudaGetSymbolAddress((void**)&wol, g_WoTl);
    cudaGetSymbolAddress((void**)&qah, g_Qah);
    cudaGetSymbolAddress((void**)&qal, g_Qal);
    cudaGetSymbolAddress((void**)&kah, g_Kah);
    cudaGetSymbolAddress((void**)&kal, g_Kal);
    cudaGetSymbolAddress((void**)&vah, g_Vah);
    cudaGetSymbolAddress((void**)&val, g_Val);

    // input + weight conversion
    split_kernel<<<(MROWS * DMODEL / 4) / 256, 256>>>(x, xh, xl);
    split_transpose_kernel<<<dim3(DMODEL/32, DMODEL/32), dim3(32,8)>>>(Wq, wqh, wql, DMODEL, DMODEL);
    split_transpose_kernel<<<dim3(DKV/32,    DMODEL/32), dim3(32,8)>>>(Wk, wkh, wkl, DMODEL, DKV);
    split_transpose_kernel<<<dim3(DKV/32,    DMODEL/32), dim3(32,8)>>>(Wv, wvh, wvl, DMODEL, DKV);
    split_transpose_kernel<<<dim3(DMODEL/32, DMODEL/32), dim3(32,8)>>>(Wo, woh, wol, DMODEL, DMODEL);

    // projections (tensor cores)
    gemm_mma<<<dim3(DMODEL/64, MROWS/64), 128>>>(xh, xl, wqh, wql, qp, DMODEL, DMODEL);
    gemm_mma<<<dim3(DKV/64,    MROWS/64), 128>>>(xh, xl, wkh, wkl, kp, DKV,    DMODEL);
    gemm_mma<<<dim3(DKV/64,    MROWS/64), 128>>>(xh, xl, wvh, wvl, vp, DKV,    DMODEL);

    // rmsnorm + rope + split to head-major bf16 (Q pre-scaled by 1/sqrt(d))
    rmsnorm_rope_split_kernel<<<(MROWS * NHEAD) / 8, 256>>>(qp, qw, cosp, sinp, NHEAD, ATT_SCALE, qah, qal);
    rmsnorm_rope_split_kernel<<<(MROWS * NKV)   / 8, 256>>>(kp, kw, cosp, sinp, NKV, 1.0f, kah, kal);
    split_v_kernel<<<(MROWS * NKV) / 8, 256>>>(vp, vah, val);

    // tensor-core flash attention
    flash_mma<<<dim3(SEQ / 64, NHEAD, BATCH), 128>>>(qah, qal, kah, kal, vah, val, yp);

    // output projection
    split_kernel<<<(MROWS * DMODEL / 4) / 256, 256>>>(yp, yh, yl);
    gemm_mma<<<dim3(DMODEL/64, MROWS/64), 128>>>(yh, yl, woh, wol, out, DMODEL, DMODEL);
}